// round 1
// baseline (speedup 1.0000x reference)
#include <cuda_runtime.h>
#include <cuda_bf16.h>

// knnLoss: B=2, downsample 64x2048 -> 32x512 (N=16384 points/batch),
// per-query top-3 NN distances (Euclidean) against 16384 refs, masked mean.
//
// Pipeline:
//   1) gather_kernel: strided downsample + pack
//        g_src[b*N+q] = (-2*sx, -2*sy, -2*sz, |s|^2 or -1 if invalid)
//        g_tgt[b*N+t] = ( tx,    ty,    tz,   |t|^2 or 1e20 if invalid (coords zeroed))
//   2) knn_partial_kernel: each block scans a 4096-target slice for 256 queries,
//        keeps top-3 smallest r = |t|^2 - 2 s.t  (monotone in d^2 per query).
//   3) merge_reduce_kernel: merge 4 slices' top-3 (12 cands), d = sqrt(max(r+|s|^2,0)),
//        deterministic block reduction of (w*sum_d, w).
//   4) finalize_kernel: per-batch sum / (3*max(cnt,1)), mean over batches.

#define NPTS   16384
#define NBATCH 2
#define TSPLIT 4
#define SLICE  (NPTS / TSPLIT)   // 4096
#define TILE   2048
#define NTHR   256
#define NCBLK  (NBATCH * NPTS / NTHR)  // 128 blocks in merge stage

__device__ float4 g_src[NBATCH * NPTS];
__device__ float4 g_tgt[NBATCH * NPTS];
__device__ float  g_partial[NBATCH * TSPLIT * NPTS * 3];
__device__ float  g_bsum[NCBLK];
__device__ float  g_bcnt[NCBLK];

__global__ void gather_kernel(const float* __restrict__ src,
                              const float* __restrict__ tgt) {
    int i = blockIdx.x * blockDim.x + threadIdx.x;   // 0 .. B*N-1
    int b = i >> 14;               // / 16384
    int n = i & (NPTS - 1);
    int h = n >> 9;                // / 512
    int w = n & 511;

    // source_pc: [B, 64, 2048, 3], sample [b, 2h, 4w, :]
    long sbase = (((long)b * 64 + 2 * h) * 2048 + 4 * w) * 3;
    float sx = src[sbase + 0];
    float sy = src[sbase + 1];
    float sz = src[sbase + 2];
    bool  vs = (sx != 0.0f) || (sy != 0.0f) || (sz != 0.0f);
    float sq = sx * sx + sy * sy + sz * sz;
    g_src[i] = make_float4(-2.0f * sx, -2.0f * sy, -2.0f * sz, vs ? sq : -1.0f);

    // target_pc: [B, 3, 64, 2048], sample [b, :, 2h, 4w]
    long tbase = (long)b * 3 * 64 * 2048 + (long)(2 * h) * 2048 + 4 * w;
    float tx = tgt[tbase];
    float ty = tgt[tbase + 64 * 2048];
    float tz = tgt[tbase + 2L * 64 * 2048];
    bool  vt = (tx != 0.0f) || (ty != 0.0f) || (tz != 0.0f);
    float tq;
    if (vt) {
        tq = tx * tx + ty * ty + tz * tz;
    } else {
        tx = 0.0f; ty = 0.0f; tz = 0.0f;
        tq = 1e20f;   // sqrt(1e20 + |s|^2) ~= 1e10 = INVALID_DIST
    }
    g_tgt[i] = make_float4(tx, ty, tz, tq);
}

__global__ __launch_bounds__(NTHR) void knn_partial_kernel() {
    __shared__ float4 tile[TILE];

    int b  = blockIdx.z;
    int ts = blockIdx.y;
    int q  = blockIdx.x * NTHR + threadIdx.x;

    float4 s = g_src[b * NPTS + q];   // (-2sx, -2sy, -2sz, sq-flag)

    float b0 = 3e38f, b1 = 3e38f, b2 = 3e38f;

    const float4* __restrict__ tbase = g_tgt + b * NPTS + ts * SLICE;

    for (int t0 = 0; t0 < SLICE; t0 += TILE) {
        for (int i = threadIdx.x; i < TILE; i += NTHR)
            tile[i] = tbase[t0 + i];
        __syncthreads();

#pragma unroll 8
        for (int j = 0; j < TILE; j++) {
            float4 t = tile[j];
            float r = fmaf(s.x, t.x, t.w);
            r = fmaf(s.y, t.y, r);
            r = fmaf(s.z, t.z, r);
            // branchless top-3 insertion (sorted b0 <= b1 <= b2)
            float m1 = fmaxf(r, b1);
            float m0 = fmaxf(r, b0);
            b2 = fminf(b2, m1);
            b1 = fminf(b1, m0);
            b0 = fminf(b0, r);
        }
        __syncthreads();
    }

    int o = ((b * TSPLIT + ts) * NPTS + q) * 3;
    g_partial[o + 0] = b0;
    g_partial[o + 1] = b1;
    g_partial[o + 2] = b2;
}

__global__ __launch_bounds__(NTHR) void merge_reduce_kernel() {
    __shared__ float ssum[NTHR];
    __shared__ float scnt[NTHR];

    int gi = blockIdx.x * NTHR + threadIdx.x;   // 0 .. B*N-1
    int b  = gi >> 14;
    int q  = gi & (NPTS - 1);

    float4 s = g_src[gi];
    float w  = (s.w >= 0.0f) ? 1.0f : 0.0f;
    float sq = fmaxf(s.w, 0.0f);

    float b0 = 3e38f, b1 = 3e38f, b2 = 3e38f;
#pragma unroll
    for (int ts = 0; ts < TSPLIT; ts++) {
        int o = ((b * TSPLIT + ts) * NPTS + q) * 3;
#pragma unroll
        for (int k = 0; k < 3; k++) {
            float r  = g_partial[o + k];
            float m1 = fmaxf(r, b1);
            float m0 = fmaxf(r, b0);
            b2 = fminf(b2, m1);
            b1 = fminf(b1, m0);
            b0 = fminf(b0, r);
        }
    }

    float d = sqrtf(fmaxf(b0 + sq, 0.0f))
            + sqrtf(fmaxf(b1 + sq, 0.0f))
            + sqrtf(fmaxf(b2 + sq, 0.0f));

    ssum[threadIdx.x] = w * d;
    scnt[threadIdx.x] = w;
    __syncthreads();
    for (int st = NTHR / 2; st > 0; st >>= 1) {
        if (threadIdx.x < st) {
            ssum[threadIdx.x] += ssum[threadIdx.x + st];
            scnt[threadIdx.x] += scnt[threadIdx.x + st];
        }
        __syncthreads();
    }
    if (threadIdx.x == 0) {
        g_bsum[blockIdx.x] = ssum[0];
        g_bcnt[blockIdx.x] = scnt[0];
    }
}

__global__ void finalize_kernel(float* __restrict__ out) {
    const int blocksPerBatch = NCBLK / NBATCH;   // 64
    float acc = 0.0f;
    for (int b = 0; b < NBATCH; b++) {
        float s = 0.0f, c = 0.0f;
        for (int i = 0; i < blocksPerBatch; i++) {
            s += g_bsum[b * blocksPerBatch + i];
            c += g_bcnt[b * blocksPerBatch + i];
        }
        acc += s / (3.0f * fmaxf(c, 1.0f));
    }
    out[0] = acc / (float)NBATCH;
}

extern "C" void kernel_launch(void* const* d_in, const int* in_sizes, int n_in,
                              void* d_out, int out_size) {
    const float* src = (const float*)d_in[0];   // source_pc [2,64,2048,3]
    const float* tgt = (const float*)d_in[1];   // target_pc [2,3,64,2048]

    gather_kernel<<<NBATCH * NPTS / NTHR, NTHR>>>(src, tgt);

    dim3 gB(NPTS / NTHR, TSPLIT, NBATCH);       // (64, 4, 2) = 512 blocks
    knn_partial_kernel<<<gB, NTHR>>>();

    merge_reduce_kernel<<<NCBLK, NTHR>>>();

    finalize_kernel<<<1, 1>>>((float*)d_out);
}

// round 2
// speedup vs baseline: 1.4306x; 1.4306x over previous
#include <cuda_runtime.h>
#include <cuda_bf16.h>

// knnLoss: B=2, downsample 64x2048 -> 32x512 (N=16384/batch),
// per-query top-3 NN Euclidean distances vs 16384 refs, masked mean.
//
// r = |t|^2 - 2 s.t is monotone in d^2 per query -> top-3 selection in r-space.
// Inner loop: 4 targets/iter via fma.rn.f32x2 on SoA shared tiles,
// branchless-min filter + rare insertion branch.

#define NPTS   16384
#define NBATCH 2
#define TSPLIT 4
#define SLICE  (NPTS / TSPLIT)   // 4096
#define TILE   1024              // targets per smem tile
#define KTHR   128               // threads in knn kernel
#define NTHR   256
#define NCBLK  (NBATCH * NPTS / NTHR)  // 128 merge blocks

__device__ float4 g_src[NBATCH * NPTS];
__device__ float  g_tx[NBATCH * NPTS];
__device__ float  g_ty[NBATCH * NPTS];
__device__ float  g_tz[NBATCH * NPTS];
__device__ float  g_tw[NBATCH * NPTS];
__device__ float  g_partial[NBATCH * TSPLIT * NPTS * 3];
__device__ float  g_bsum[NCBLK];
__device__ float  g_bcnt[NCBLK];

#define FMA2(d, a, b, c) \
    asm("fma.rn.f32x2 %0, %1, %2, %3;" : "=l"(d) : "l"(a), "l"(b), "l"(c))
#define UNPK2(lo, hi, v) \
    asm("mov.b64 {%0, %1}, %2;" : "=f"(lo), "=f"(hi) : "l"(v))
#define DUP2(d, f) \
    asm("mov.b64 %0, {%1, %1};" : "=l"(d) : "f"(f))

__global__ void gather_kernel(const float* __restrict__ src,
                              const float* __restrict__ tgt) {
    int i = blockIdx.x * blockDim.x + threadIdx.x;   // 0 .. B*N-1
    int b = i >> 14;
    int n = i & (NPTS - 1);
    int h = n >> 9;
    int w = n & 511;

    // source_pc: [B, 64, 2048, 3], sample [b, 2h, 4w, :]
    long sbase = (((long)b * 64 + 2 * h) * 2048 + 4 * w) * 3;
    float sx = src[sbase + 0];
    float sy = src[sbase + 1];
    float sz = src[sbase + 2];
    bool  vs = (sx != 0.0f) || (sy != 0.0f) || (sz != 0.0f);
    float sq = sx * sx + sy * sy + sz * sz;
    g_src[i] = make_float4(-2.0f * sx, -2.0f * sy, -2.0f * sz, vs ? sq : -1.0f);

    // target_pc: [B, 3, 64, 2048], sample [b, :, 2h, 4w]
    long tbase = (long)b * 3 * 64 * 2048 + (long)(2 * h) * 2048 + 4 * w;
    float tx = tgt[tbase];
    float ty = tgt[tbase + 64 * 2048];
    float tz = tgt[tbase + 2L * 64 * 2048];
    bool  vt = (tx != 0.0f) || (ty != 0.0f) || (tz != 0.0f);
    float tq;
    if (vt) {
        tq = tx * tx + ty * ty + tz * tz;
    } else {
        tx = 0.0f; ty = 0.0f; tz = 0.0f;
        tq = 1e20f;   // sqrt(1e20) ~= 1e10 = INVALID_DIST
    }
    g_tx[i] = tx; g_ty[i] = ty; g_tz[i] = tz; g_tw[i] = tq;
}

__device__ __forceinline__ void top3_insert(float r, float& b0, float& b1, float& b2) {
    float m1 = fmaxf(r, b1);
    float m0 = fmaxf(r, b0);
    b2 = fminf(b2, m1);
    b1 = fminf(b1, m0);
    b0 = fminf(b0, r);
}

__global__ __launch_bounds__(KTHR, 8) void knn_partial_kernel() {
    __shared__ ulonglong2 s_x[TILE / 4];
    __shared__ ulonglong2 s_y[TILE / 4];
    __shared__ ulonglong2 s_z[TILE / 4];
    __shared__ ulonglong2 s_w[TILE / 4];

    int b  = blockIdx.z;
    int ts = blockIdx.y;
    int q  = blockIdx.x * KTHR + threadIdx.x;

    float4 s = g_src[b * NPTS + q];   // (-2sx, -2sy, -2sz, sq-flag)
    unsigned long long sxx, syy, szz;
    DUP2(sxx, s.x);
    DUP2(syy, s.y);
    DUP2(szz, s.z);

    float b0 = 3e38f, b1 = 3e38f, b2 = 3e38f;

    int base = b * NPTS + ts * SLICE;

    for (int t0 = 0; t0 < SLICE; t0 += TILE) {
        const float4* gx = (const float4*)(g_tx + base + t0);
        const float4* gy = (const float4*)(g_ty + base + t0);
        const float4* gz = (const float4*)(g_tz + base + t0);
        const float4* gw = (const float4*)(g_tw + base + t0);
        for (int i = threadIdx.x; i < TILE / 4; i += KTHR) {
            float4 vx = gx[i]; s_x[i] = *(const ulonglong2*)&vx;
            float4 vy = gy[i]; s_y[i] = *(const ulonglong2*)&vy;
            float4 vz = gz[i]; s_z[i] = *(const ulonglong2*)&vz;
            float4 vw = gw[i]; s_w[i] = *(const ulonglong2*)&vw;
        }
        __syncthreads();

#pragma unroll 2
        for (int j = 0; j < TILE / 4; j++) {
            ulonglong2 xv = s_x[j];
            ulonglong2 yv = s_y[j];
            ulonglong2 zv = s_z[j];
            ulonglong2 wv = s_w[j];
            unsigned long long rA, rB;
            FMA2(rA, sxx, xv.x, wv.x);
            FMA2(rB, sxx, xv.y, wv.y);
            FMA2(rA, syy, yv.x, rA);
            FMA2(rB, syy, yv.y, rB);
            FMA2(rA, szz, zv.x, rA);
            FMA2(rB, szz, zv.y, rB);
            float r0, r1, r2, r3;
            UNPK2(r0, r1, rA);
            UNPK2(r2, r3, rB);
            float m = fminf(fminf(r0, r1), fminf(r2, r3));
            if (m < b2) {
                top3_insert(r0, b0, b1, b2);
                top3_insert(r1, b0, b1, b2);
                top3_insert(r2, b0, b1, b2);
                top3_insert(r3, b0, b1, b2);
            }
        }
        __syncthreads();
    }

    int o = ((b * TSPLIT + ts) * NPTS + q) * 3;
    g_partial[o + 0] = b0;
    g_partial[o + 1] = b1;
    g_partial[o + 2] = b2;
}

__global__ __launch_bounds__(NTHR) void merge_reduce_kernel() {
    __shared__ float ssum[NTHR];
    __shared__ float scnt[NTHR];

    int gi = blockIdx.x * NTHR + threadIdx.x;   // 0 .. B*N-1
    int b  = gi >> 14;
    int q  = gi & (NPTS - 1);

    float4 s = g_src[gi];
    float w  = (s.w >= 0.0f) ? 1.0f : 0.0f;
    float sq = fmaxf(s.w, 0.0f);

    float b0 = 3e38f, b1 = 3e38f, b2 = 3e38f;
#pragma unroll
    for (int ts = 0; ts < TSPLIT; ts++) {
        int o = ((b * TSPLIT + ts) * NPTS + q) * 3;
#pragma unroll
        for (int k = 0; k < 3; k++) {
            float r = g_partial[o + k];
            top3_insert(r, b0, b1, b2);
        }
    }

    float d = sqrtf(fmaxf(b0 + sq, 0.0f))
            + sqrtf(fmaxf(b1 + sq, 0.0f))
            + sqrtf(fmaxf(b2 + sq, 0.0f));

    ssum[threadIdx.x] = w * d;
    scnt[threadIdx.x] = w;
    __syncthreads();
    for (int st = NTHR / 2; st > 0; st >>= 1) {
        if (threadIdx.x < st) {
            ssum[threadIdx.x] += ssum[threadIdx.x + st];
            scnt[threadIdx.x] += scnt[threadIdx.x + st];
        }
        __syncthreads();
    }
    if (threadIdx.x == 0) {
        g_bsum[blockIdx.x] = ssum[0];
        g_bcnt[blockIdx.x] = scnt[0];
    }
}

__global__ __launch_bounds__(NCBLK) void finalize_kernel(float* __restrict__ out) {
    __shared__ float ssum[NCBLK];
    __shared__ float scnt[NCBLK];
    int t = threadIdx.x;           // 0..127, [0,64)=batch0, [64,128)=batch1
    ssum[t] = g_bsum[t];
    scnt[t] = g_bcnt[t];
    __syncthreads();
    for (int st = 32; st > 0; st >>= 1) {
        if ((t & 63) < st) {
            ssum[t] += ssum[t + st];
            scnt[t] += scnt[t + st];
        }
        __syncthreads();
    }
    if (t == 0) {
        float acc = ssum[0]  / (3.0f * fmaxf(scnt[0],  1.0f))
                  + ssum[64] / (3.0f * fmaxf(scnt[64], 1.0f));
        out[0] = acc * 0.5f;
    }
}

extern "C" void kernel_launch(void* const* d_in, const int* in_sizes, int n_in,
                              void* d_out, int out_size) {
    const float* src = (const float*)d_in[0];   // source_pc [2,64,2048,3]
    const float* tgt = (const float*)d_in[1];   // target_pc [2,3,64,2048]

    gather_kernel<<<NBATCH * NPTS / NTHR, NTHR>>>(src, tgt);

    dim3 gB(NPTS / KTHR, TSPLIT, NBATCH);       // (128, 4, 2) = 1024 blocks
    knn_partial_kernel<<<gB, KTHR>>>();

    merge_reduce_kernel<<<NCBLK, NTHR>>>();

    finalize_kernel<<<1, NCBLK>>>((float*)d_out);
}

// round 3
// speedup vs baseline: 1.4437x; 1.0092x over previous
#include <cuda_runtime.h>
#include <cuda_bf16.h>

// knnLoss: B=2, downsample 64x2048 -> 32x512 (N=16384/batch),
// per-query top-3 NN Euclidean distances vs 16384 refs, masked mean.
//
// r = |t|^2 - 2 s.t is monotone in d^2 per query -> top-3 selection in r-space.
// Inner loop: 4 targets/iter via fma.rn.f32x2 on SoA shared tiles,
// 2 queries per thread (amortizes broadcast LDS + loop overhead),
// per-query min-tree filter + rare scalar insertion.

#define NPTS   16384
#define NBATCH 2
#define TSPLIT 4
#define SLICE  (NPTS / TSPLIT)   // 4096
#define TILE   2048              // targets per smem tile (32KB SoA)
#define KTHR   128               // threads in knn kernel
#define QPT    2                 // queries per thread
#define QPB    (KTHR * QPT)      // 256 queries per block
#define NTHR   256
#define NCBLK  (NBATCH * NPTS / NTHR)  // 128 merge blocks

__device__ float4 g_src[NBATCH * NPTS];
__device__ float  g_tx[NBATCH * NPTS];
__device__ float  g_ty[NBATCH * NPTS];
__device__ float  g_tz[NBATCH * NPTS];
__device__ float  g_tw[NBATCH * NPTS];
__device__ float  g_partial[NBATCH * TSPLIT * NPTS * 3];
__device__ float  g_bsum[NCBLK];
__device__ float  g_bcnt[NCBLK];

#define FMA2(d, a, b, c) \
    asm("fma.rn.f32x2 %0, %1, %2, %3;" : "=l"(d) : "l"(a), "l"(b), "l"(c))
#define UNPK2(lo, hi, v) \
    asm("mov.b64 {%0, %1}, %2;" : "=f"(lo), "=f"(hi) : "l"(v))
#define DUP2(d, f) \
    asm("mov.b64 %0, {%1, %1};" : "=l"(d) : "f"(f))

__global__ void gather_kernel(const float* __restrict__ src,
                              const float* __restrict__ tgt) {
    int i = blockIdx.x * blockDim.x + threadIdx.x;   // 0 .. B*N-1
    int b = i >> 14;
    int n = i & (NPTS - 1);
    int h = n >> 9;
    int w = n & 511;

    // source_pc: [B, 64, 2048, 3], sample [b, 2h, 4w, :]
    long sbase = (((long)b * 64 + 2 * h) * 2048 + 4 * w) * 3;
    float sx = src[sbase + 0];
    float sy = src[sbase + 1];
    float sz = src[sbase + 2];
    bool  vs = (sx != 0.0f) || (sy != 0.0f) || (sz != 0.0f);
    float sq = sx * sx + sy * sy + sz * sz;
    g_src[i] = make_float4(-2.0f * sx, -2.0f * sy, -2.0f * sz, vs ? sq : -1.0f);

    // target_pc: [B, 3, 64, 2048], sample [b, :, 2h, 4w]
    long tbase = (long)b * 3 * 64 * 2048 + (long)(2 * h) * 2048 + 4 * w;
    float tx = tgt[tbase];
    float ty = tgt[tbase + 64 * 2048];
    float tz = tgt[tbase + 2L * 64 * 2048];
    bool  vt = (tx != 0.0f) || (ty != 0.0f) || (tz != 0.0f);
    float tq;
    if (vt) {
        tq = tx * tx + ty * ty + tz * tz;
    } else {
        tx = 0.0f; ty = 0.0f; tz = 0.0f;
        tq = 1e20f;   // sqrt(1e20) ~= 1e10 = INVALID_DIST
    }
    g_tx[i] = tx; g_ty[i] = ty; g_tz[i] = tz; g_tw[i] = tq;
}

__device__ __forceinline__ void top3_insert(float r, float& b0, float& b1, float& b2) {
    float m1 = fmaxf(r, b1);
    float m0 = fmaxf(r, b0);
    b2 = fminf(b2, m1);
    b1 = fminf(b1, m0);
    b0 = fminf(b0, r);
}

__global__ __launch_bounds__(KTHR, 3) void knn_partial_kernel() {
    __shared__ ulonglong2 s_x[TILE / 4];
    __shared__ ulonglong2 s_y[TILE / 4];
    __shared__ ulonglong2 s_z[TILE / 4];
    __shared__ ulonglong2 s_w[TILE / 4];

    int b  = blockIdx.z;
    int ts = blockIdx.y;
    int q0 = blockIdx.x * QPB + threadIdx.x;        // first query
    int q1 = q0 + KTHR;                             // second query

    float4 sA = g_src[b * NPTS + q0];   // (-2sx, -2sy, -2sz, sq-flag)
    float4 sB = g_src[b * NPTS + q1];
    unsigned long long ax, ay, az, bx, by, bz;
    DUP2(ax, sA.x); DUP2(ay, sA.y); DUP2(az, sA.z);
    DUP2(bx, sB.x); DUP2(by, sB.y); DUP2(bz, sB.z);

    float a0 = 3e38f, a1 = 3e38f, a2 = 3e38f;       // top-3 for q0
    float c0 = 3e38f, c1 = 3e38f, c2 = 3e38f;       // top-3 for q1

    int base = b * NPTS + ts * SLICE;

    for (int t0 = 0; t0 < SLICE; t0 += TILE) {
        const float4* gx = (const float4*)(g_tx + base + t0);
        const float4* gy = (const float4*)(g_ty + base + t0);
        const float4* gz = (const float4*)(g_tz + base + t0);
        const float4* gw = (const float4*)(g_tw + base + t0);
        for (int i = threadIdx.x; i < TILE / 4; i += KTHR) {
            float4 vx = gx[i]; s_x[i] = *(const ulonglong2*)&vx;
            float4 vy = gy[i]; s_y[i] = *(const ulonglong2*)&vy;
            float4 vz = gz[i]; s_z[i] = *(const ulonglong2*)&vz;
            float4 vw = gw[i]; s_w[i] = *(const ulonglong2*)&vw;
        }
        __syncthreads();

#pragma unroll 4
        for (int j = 0; j < TILE / 4; j++) {
            ulonglong2 xv = s_x[j];
            ulonglong2 yv = s_y[j];
            ulonglong2 zv = s_z[j];
            ulonglong2 wv = s_w[j];

            unsigned long long rA0, rB0, rA1, rB1;
            FMA2(rA0, ax, xv.x, wv.x);
            FMA2(rB0, ax, xv.y, wv.y);
            FMA2(rA1, bx, xv.x, wv.x);
            FMA2(rB1, bx, xv.y, wv.y);
            FMA2(rA0, ay, yv.x, rA0);
            FMA2(rB0, ay, yv.y, rB0);
            FMA2(rA1, by, yv.x, rA1);
            FMA2(rB1, by, yv.y, rB1);
            FMA2(rA0, az, zv.x, rA0);
            FMA2(rB0, az, zv.y, rB0);
            FMA2(rA1, bz, zv.x, rA1);
            FMA2(rB1, bz, zv.y, rB1);

            float r0, r1, r2, r3;
            UNPK2(r0, r1, rA0);
            UNPK2(r2, r3, rB0);
            float m = fminf(fminf(r0, r1), fminf(r2, r3));
            if (m < a2) {
                top3_insert(r0, a0, a1, a2);
                top3_insert(r1, a0, a1, a2);
                top3_insert(r2, a0, a1, a2);
                top3_insert(r3, a0, a1, a2);
            }

            float u0, u1, u2, u3;
            UNPK2(u0, u1, rA1);
            UNPK2(u2, u3, rB1);
            float mu = fminf(fminf(u0, u1), fminf(u2, u3));
            if (mu < c2) {
                top3_insert(u0, c0, c1, c2);
                top3_insert(u1, c0, c1, c2);
                top3_insert(u2, c0, c1, c2);
                top3_insert(u3, c0, c1, c2);
            }
        }
        __syncthreads();
    }

    int o0 = ((b * TSPLIT + ts) * NPTS + q0) * 3;
    g_partial[o0 + 0] = a0;
    g_partial[o0 + 1] = a1;
    g_partial[o0 + 2] = a2;
    int o1 = ((b * TSPLIT + ts) * NPTS + q1) * 3;
    g_partial[o1 + 0] = c0;
    g_partial[o1 + 1] = c1;
    g_partial[o1 + 2] = c2;
}

__global__ __launch_bounds__(NTHR) void merge_reduce_kernel() {
    __shared__ float ssum[NTHR];
    __shared__ float scnt[NTHR];

    int gi = blockIdx.x * NTHR + threadIdx.x;   // 0 .. B*N-1
    int b  = gi >> 14;
    int q  = gi & (NPTS - 1);

    float4 s = g_src[gi];
    float w  = (s.w >= 0.0f) ? 1.0f : 0.0f;
    float sq = fmaxf(s.w, 0.0f);

    float b0 = 3e38f, b1 = 3e38f, b2 = 3e38f;
#pragma unroll
    for (int ts = 0; ts < TSPLIT; ts++) {
        int o = ((b * TSPLIT + ts) * NPTS + q) * 3;
#pragma unroll
        for (int k = 0; k < 3; k++) {
            float r = g_partial[o + k];
            top3_insert(r, b0, b1, b2);
        }
    }

    float d = sqrtf(fmaxf(b0 + sq, 0.0f))
            + sqrtf(fmaxf(b1 + sq, 0.0f))
            + sqrtf(fmaxf(b2 + sq, 0.0f));

    ssum[threadIdx.x] = w * d;
    scnt[threadIdx.x] = w;
    __syncthreads();
    for (int st = NTHR / 2; st > 0; st >>= 1) {
        if (threadIdx.x < st) {
            ssum[threadIdx.x] += ssum[threadIdx.x + st];
            scnt[threadIdx.x] += scnt[threadIdx.x + st];
        }
        __syncthreads();
    }
    if (threadIdx.x == 0) {
        g_bsum[blockIdx.x] = ssum[0];
        g_bcnt[blockIdx.x] = scnt[0];
    }
}

__global__ __launch_bounds__(NCBLK) void finalize_kernel(float* __restrict__ out) {
    __shared__ float ssum[NCBLK];
    __shared__ float scnt[NCBLK];
    int t = threadIdx.x;           // 0..127, [0,64)=batch0, [64,128)=batch1
    ssum[t] = g_bsum[t];
    scnt[t] = g_bcnt[t];
    __syncthreads();
    for (int st = 32; st > 0; st >>= 1) {
        if ((t & 63) < st) {
            ssum[t] += ssum[t + st];
            scnt[t] += scnt[t + st];
        }
        __syncthreads();
    }
    if (t == 0) {
        float acc = ssum[0]  / (3.0f * fmaxf(scnt[0],  1.0f))
                  + ssum[64] / (3.0f * fmaxf(scnt[64], 1.0f));
        out[0] = acc * 0.5f;
    }
}

extern "C" void kernel_launch(void* const* d_in, const int* in_sizes, int n_in,
                              void* d_out, int out_size) {
    const float* src = (const float*)d_in[0];   // source_pc [2,64,2048,3]
    const float* tgt = (const float*)d_in[1];   // target_pc [2,3,64,2048]

    gather_kernel<<<NBATCH * NPTS / NTHR, NTHR>>>(src, tgt);

    dim3 gB(NPTS / QPB, TSPLIT, NBATCH);        // (64, 4, 2) = 512 blocks
    knn_partial_kernel<<<gB, KTHR>>>();

    merge_reduce_kernel<<<NCBLK, NTHR>>>();

    finalize_kernel<<<1, NCBLK>>>((float*)d_out);
}